// round 7
// baseline (speedup 1.0000x reference)
#include <cuda_runtime.h>

#define TT 400000
#define HIDN 20
#define G4 80
#define INDIM 40

// Static device scratch (no dynamic allocation allowed).
__device__ float g_pre0[TT * G4];   // fused layer-0 pre-activations [T,80] (128 MB)
__device__ float g_h1buf[TT * HIDN]; // h1 per step for the parallel output pass (32 MB)
__device__ float g_M[G4 * INDIM];   // fused (W_ih0 @ W_inp) [80,40]
__device__ float g_b0[G4];          // fused layer-0 bias
__device__ float g_b1[G4];          // b_ih1 + b_hh1

// ---------------------------------------------------------------------------
// Prep: fuse input projection into layer-0 input matmul.
//   pre0[t,g] = sum_k in[t,k] * M[g,k] + b0[g]
//   M[g,k]    = sum_e W_ih0[g,e] * W_inp[e,k]
//   b0[g]     = b_ih0[g] + b_hh0[g] + sum_e W_ih0[g,e] * b_inp[e]
// ---------------------------------------------------------------------------
__global__ void prep_kernel(const float* __restrict__ W_inp,
                            const float* __restrict__ b_inp,
                            const float* __restrict__ W_ih0,
                            const float* __restrict__ b_ih0,
                            const float* __restrict__ b_hh0,
                            const float* __restrict__ b_ih1,
                            const float* __restrict__ b_hh1) {
    int tid = threadIdx.x;
    if (tid < G4) {
        g_b1[tid] = b_ih1[tid] + b_hh1[tid];
        float s = b_ih0[tid] + b_hh0[tid];
        #pragma unroll
        for (int e = 0; e < HIDN; e++) s += W_ih0[tid * HIDN + e] * b_inp[e];
        g_b0[tid] = s;
    }
    for (int idx = tid; idx < G4 * INDIM; idx += blockDim.x) {
        int g = idx / INDIM, k = idx % INDIM;
        float s = 0.f;
        #pragma unroll
        for (int e = 0; e < HIDN; e++) s += W_ih0[g * HIDN + e] * W_inp[e * INDIM + k];
        g_M[idx] = s;
    }
}

// ---------------------------------------------------------------------------
// Parallel pass: pre0 for all T timesteps. Block = 320 threads = 4 rows x 80 cols.
// M staged in shared with 41-float row pitch (conflict-free across g lanes).
// ---------------------------------------------------------------------------
__global__ __launch_bounds__(320) void pre0_kernel(const float* __restrict__ in_states) {
    __shared__ float sM[G4 * 41];
    __shared__ float sB[G4];
    __shared__ float sIn[4 * INDIM];
    int tid = threadIdx.x;
    for (int idx = tid; idx < G4 * INDIM; idx += 320)
        sM[(idx / INDIM) * 41 + (idx % INDIM)] = g_M[idx];
    if (tid < G4) sB[tid] = g_b0[tid];
    if (tid < 4 * INDIM) sIn[tid] = in_states[blockIdx.x * 4 * INDIM + tid];
    __syncthreads();

    int r = tid / G4;   // 0..3
    int g = tid % G4;
    float acc = sB[g];
    #pragma unroll
    for (int k = 0; k < INDIM; k++) acc += sIn[r * INDIM + k] * sM[g * 41 + k];
    g_pre0[(blockIdx.x * 4 + r) * G4 + g] = acc;
}

// ---------------------------------------------------------------------------
// Fast activations: one EX2 + one MUFU.RCP each.
//   sigmoid(x) = 1/(1+exp(-x));  tanh(x) = 2*sigmoid(2x) - 1  (branch-free)
// Saturates correctly via inf/0 behavior of __expf/__fdividef.
// ---------------------------------------------------------------------------
__device__ __forceinline__ float act_sig(float a, float ns, float mul, float add) {
    float e = __expf(a * ns);
    float s = __fdividef(1.0f, 1.0f + e);
    return fmaf(s, mul, add);
}
__device__ __forceinline__ float fast_tanh(float a) { return act_sig(a, -2.f, 2.f, -1.f); }

__device__ __forceinline__ void ld20(float* d, const float* s) {
    const float4* s4 = reinterpret_cast<const float4*>(s);
    #pragma unroll
    for (int i = 0; i < 5; i++) {
        float4 v = s4[i];
        d[4 * i] = v.x; d[4 * i + 1] = v.y; d[4 * i + 2] = v.z; d[4 * i + 3] = v.w;
    }
}

// ---------------------------------------------------------------------------
// Serial recurrence. 224 threads:
//   tid   0..127 : 4 gate warps. Warp w owns units u = 5w..5w+4.
//                  lane = 5*sect + u_local, gate g = sect*20 + u (sect: i,f,g,o).
//                  Gate->cell exchange is in-warp via SHFL; c replicated per sect.
//   tid 128..207 : part1[g] = b1[g] + W_hh1[g,:] . h1_{t-1}  (overlaps layer 0)
//   2 __syncthreads per step. pre0 prefetched 2 steps ahead.
// ---------------------------------------------------------------------------
__global__ __launch_bounds__(224, 1) void lstm_seq_kernel(
        const float* __restrict__ W_hh0,
        const float* __restrict__ W_ih1,
        const float* __restrict__ W_hh1,
        float* __restrict__ out_tail)   // d_out + TT : [h0(20), h1(20), c0(20), c1(20)]
{
    __shared__ __align__(16) float sh_h0[2][HIDN];  // ping-pong
    __shared__ __align__(16) float sh_h1[HIDN];
    __shared__ __align__(16) float sh_p[G4];

    const int tid  = threadIdx.x;
    const int lane = tid & 31;
    const int w    = tid >> 5;

    float w0[HIDN], wi1[HIDN], wh1[HIDN];
    float b1 = 0.f;
    int g = 0, u = 0, u_local = 0;
    float ns = -1.f, amul = 1.f, aadd = 0.f;

    if (tid < 128) {
        u_local = lane % 5;
        int sect = lane / 5;
        u = w * 5 + u_local;
        g = (lane < 20) ? (sect * 20 + u) : 0;   // lanes 20..31 compute harmless dupes
        if (sect == 2) { ns = -2.f; amul = 2.f; aadd = -1.f; }  // g-gate = tanh
        #pragma unroll
        for (int k = 0; k < HIDN; k++) {
            w0[k]  = __ldg(&W_hh0[g * HIDN + k]);
            wi1[k] = __ldg(&W_ih1[g * HIDN + k]);
        }
    } else if (tid < 208) {
        int gq = tid - 128;
        b1 = g_b1[gq];
        #pragma unroll
        for (int k = 0; k < HIDN; k++) wh1[k] = __ldg(&W_hh1[gq * HIDN + k]);
    }

    if (tid < HIDN) { sh_h0[0][tid] = 0.f; sh_h0[1][tid] = 0.f; sh_h1[tid] = 0.f; }
    __syncthreads();

    float c0 = 0.f, c1 = 0.f, h0r = 0.f, h1r = 0.f;
    float pcur = 0.f, pnext = 0.f;
    if (tid < 128) {
        pcur  = __ldg(&g_pre0[0 * G4 + g]);
        pnext = __ldg(&g_pre0[1 * G4 + g]);
    }
    int pp = 0;

    for (int t = 0; t < TT; t++) {
        // ---- Phase A: layer-0 cell (gate warps)  ||  part1 = Whh1 . h1_prev ----
        if (tid < 128) {
            float hb[HIDN];
            ld20(hb, sh_h0[pp]);                  // h0_{t-1}
            float a = pcur;                        // pre0 includes both biases
            #pragma unroll
            for (int k = 0; k < HIDN; k++) a = fmaf(w0[k], hb[k], a);
            float act = act_sig(a, ns, amul, aadd);
            float iv = __shfl_sync(0xFFFFFFFFu, act, u_local);
            float fv = __shfl_sync(0xFFFFFFFFu, act, u_local + 5);
            float gv = __shfl_sync(0xFFFFFFFFu, act, u_local + 10);
            float ov = __shfl_sync(0xFFFFFFFFu, act, u_local + 15);
            c0 = fmaf(fv, c0, iv * gv);            // replicated across sect lanes
            h0r = ov * fast_tanh(c0);
            if (lane < 5) sh_h0[pp ^ 1][u] = h0r;  // sect==0 lanes publish
            pcur  = pnext;                          // 2-deep pre0 prefetch
            pnext = (t + 2 < TT) ? __ldg(&g_pre0[(t + 2) * G4 + g]) : 0.f;
        } else if (tid < 208) {
            float hb[HIDN];
            ld20(hb, sh_h1);                       // h1_{t-1}
            float p = b1;
            #pragma unroll
            for (int k = 0; k < HIDN; k++) p = fmaf(wh1[k], hb[k], p);
            sh_p[tid - 128] = p;
        }
        __syncthreads();  // sync1: h0_t + part1 published

        // ---- Phase B: layer-1 cell ----
        if (tid < 128) {
            float hb[HIDN];
            ld20(hb, sh_h0[pp ^ 1]);               // h0_t
            float b = sh_p[g];
            #pragma unroll
            for (int k = 0; k < HIDN; k++) b = fmaf(wi1[k], hb[k], b);
            float act = act_sig(b, ns, amul, aadd);
            float iv = __shfl_sync(0xFFFFFFFFu, act, u_local);
            float fv = __shfl_sync(0xFFFFFFFFu, act, u_local + 5);
            float gv = __shfl_sync(0xFFFFFFFFu, act, u_local + 10);
            float ov = __shfl_sync(0xFFFFFFFFu, act, u_local + 15);
            c1 = fmaf(fv, c1, iv * gv);
            h1r = ov * fast_tanh(c1);
            if (lane < 5) {
                sh_h1[u] = h1r;
                g_h1buf[t * HIDN + u] = h1r;       // fire-and-forget store
            }
        }
        __syncthreads();  // sync2: h1_t published (guards next step's readers)
        pp ^= 1;
    }

    if (tid < 128 && lane < 5) {                   // final states: h_n then c_n
        out_tail[u]            = h0r;
        out_tail[HIDN + u]     = h1r;
        out_tail[2 * HIDN + u] = c0;
        out_tail[3 * HIDN + u] = c1;
    }
}

// ---------------------------------------------------------------------------
// Parallel output pass: out[t] = h1[t] . W_out + b_out
// ---------------------------------------------------------------------------
__global__ void out_kernel(const float* __restrict__ W_out,
                           const float* __restrict__ b_out,
                           float* __restrict__ out) {
    int t = blockIdx.x * blockDim.x + threadIdx.x;
    if (t >= TT) return;
    float wv[HIDN];
    #pragma unroll
    for (int k = 0; k < HIDN; k++) wv[k] = __ldg(&W_out[k]);
    const float4* h4 = reinterpret_cast<const float4*>(&g_h1buf[t * HIDN]);
    float acc = __ldg(b_out);
    #pragma unroll
    for (int i = 0; i < 5; i++) {
        float4 v = __ldg(&h4[i]);
        acc += wv[4 * i] * v.x + wv[4 * i + 1] * v.y
             + wv[4 * i + 2] * v.z + wv[4 * i + 3] * v.w;
    }
    out[t] = acc;
}

extern "C" void kernel_launch(void* const* d_in, const int* in_sizes, int n_in,
                              void* d_out, int out_size) {
    const float* in_states = (const float*)d_in[0];
    const float* W_inp     = (const float*)d_in[1];
    const float* b_inp     = (const float*)d_in[2];
    const float* W_ih0     = (const float*)d_in[3];
    const float* W_hh0     = (const float*)d_in[4];
    const float* b_ih0     = (const float*)d_in[5];
    const float* b_hh0     = (const float*)d_in[6];
    const float* W_ih1     = (const float*)d_in[7];
    const float* W_hh1     = (const float*)d_in[8];
    const float* b_ih1     = (const float*)d_in[9];
    const float* b_hh1     = (const float*)d_in[10];
    const float* W_out     = (const float*)d_in[11];
    const float* b_out     = (const float*)d_in[12];
    float* out = (float*)d_out;

    prep_kernel<<<1, 128>>>(W_inp, b_inp, W_ih0, b_ih0, b_hh0, b_ih1, b_hh1);
    pre0_kernel<<<TT / 4, 320>>>(in_states);
    lstm_seq_kernel<<<1, 224>>>(W_hh0, W_ih1, W_hh1, out + TT);
    out_kernel<<<(TT + 255) / 256, 256>>>(W_out, b_out, out);
}

// round 8
// speedup vs baseline: 1.3383x; 1.3383x over previous
#include <cuda_runtime.h>

#define TT 400000
#define HIDN 20
#define G4 80
#define INDIM 40

// Static device scratch (no dynamic allocation allowed).
__device__ float g_pre0[TT * G4];    // fused layer-0 pre-activations [T,80] (128 MB)
__device__ float g_h1buf[TT * HIDN]; // h1 per step for the parallel output pass (32 MB)
__device__ float g_M[G4 * INDIM];    // fused (W_ih0 @ W_inp) [80,40]
__device__ float g_b0[G4];           // fused layer-0 bias
__device__ float g_b1[G4];           // b_ih1 + b_hh1

// ---------------------------------------------------------------------------
// Prep: fuse input projection into layer-0 input matmul.
// ---------------------------------------------------------------------------
__global__ void prep_kernel(const float* __restrict__ W_inp,
                            const float* __restrict__ b_inp,
                            const float* __restrict__ W_ih0,
                            const float* __restrict__ b_ih0,
                            const float* __restrict__ b_hh0,
                            const float* __restrict__ b_ih1,
                            const float* __restrict__ b_hh1) {
    int tid = threadIdx.x;
    if (tid < G4) {
        g_b1[tid] = b_ih1[tid] + b_hh1[tid];
        float s = b_ih0[tid] + b_hh0[tid];
        #pragma unroll
        for (int e = 0; e < HIDN; e++) s += W_ih0[tid * HIDN + e] * b_inp[e];
        g_b0[tid] = s;
    }
    for (int idx = tid; idx < G4 * INDIM; idx += blockDim.x) {
        int g = idx / INDIM, k = idx % INDIM;
        float s = 0.f;
        #pragma unroll
        for (int e = 0; e < HIDN; e++) s += W_ih0[g * HIDN + e] * W_inp[e * INDIM + k];
        g_M[idx] = s;
    }
}

// ---------------------------------------------------------------------------
// Parallel pass: pre0 for all T timesteps. Block = 320 threads = 4 rows x 80 cols.
// ---------------------------------------------------------------------------
__global__ __launch_bounds__(320) void pre0_kernel(const float* __restrict__ in_states) {
    __shared__ float sM[G4 * 41];
    __shared__ float sB[G4];
    __shared__ float sIn[4 * INDIM];
    int tid = threadIdx.x;
    for (int idx = tid; idx < G4 * INDIM; idx += 320)
        sM[(idx / INDIM) * 41 + (idx % INDIM)] = g_M[idx];
    if (tid < G4) sB[tid] = g_b0[tid];
    if (tid < 4 * INDIM) sIn[tid] = in_states[blockIdx.x * 4 * INDIM + tid];
    __syncthreads();

    int r = tid / G4;
    int g = tid % G4;
    float acc = sB[g];
    #pragma unroll
    for (int k = 0; k < INDIM; k++) acc += sIn[r * INDIM + k] * sM[g * 41 + k];
    g_pre0[(blockIdx.x * 4 + r) * G4 + g] = acc;
}

// ---------------------------------------------------------------------------
// Fast activations: ex2.approx + rcp.approx (pinned via PTX).
//   sigmoid(x) = rcp(1 + ex2(-x*log2e));  tanh(x) = 2*sigmoid(2x) - 1
// Saturates correctly via inf/0 behavior.
// ---------------------------------------------------------------------------
__device__ __forceinline__ float ex2f(float x) {
    float y; asm("ex2.approx.f32 %0, %1;" : "=f"(y) : "f"(x)); return y;
}
__device__ __forceinline__ float rcpf(float x) {
    float y; asm("rcp.approx.f32 %0, %1;" : "=f"(y) : "f"(x)); return y;
}
// ns = -log2e for sigmoid, -2*log2e for tanh form
__device__ __forceinline__ float act_sig(float a, float ns, float mul, float add) {
    float s = rcpf(1.0f + ex2f(a * ns));
    return fmaf(s, mul, add);
}
#define NS_SIG  (-1.4426950408889634f)
#define NS_TANH (-2.8853900817779268f)
__device__ __forceinline__ float fast_tanh(float a) { return act_sig(a, NS_TANH, 2.f, -1.f); }

__device__ __forceinline__ void ld20(float* d, const float* s) {
    const float4* s4 = reinterpret_cast<const float4*>(s);
    #pragma unroll
    for (int i = 0; i < 5; i++) {
        float4 v = s4[i];
        d[4 * i] = v.x; d[4 * i + 1] = v.y; d[4 * i + 2] = v.z; d[4 * i + 3] = v.w;
    }
}

// ---------------------------------------------------------------------------
// Serial recurrence, software-pipelined across layers. 128 threads = 4 warps.
//   Warp w owns units u = 5w..5w+4. lane = 5*sect + u_local, gate g = sect*20+u
//   (sect order: i,f,g,o). Gate->cell exchange in-warp via SHFL; c replicated.
//   Iteration t computes h0(t) AND h1(t-1) concurrently (independent chains),
//   ONE __syncthreads per iteration (ping-pong buffers make one barrier safe).
// ---------------------------------------------------------------------------
__global__ __launch_bounds__(128, 1) void lstm_seq_kernel(
        const float* __restrict__ W_hh0,
        const float* __restrict__ W_ih1,
        const float* __restrict__ W_hh1,
        float* __restrict__ out_tail)   // d_out + TT : [h0(20), h1(20), c0(20), c1(20)]
{
    __shared__ __align__(16) float sh_h0[2][HIDN];  // ping-pong
    __shared__ __align__(16) float sh_h1[2][HIDN];  // ping-pong

    const int tid     = threadIdx.x;
    const int lane    = tid & 31;
    const int w       = tid >> 5;
    const int u_local = lane % 5;
    const int sect    = lane / 5;
    const int u       = w * 5 + u_local;
    // lanes 20..31 compute harmless duplicates of the i-gate (sect 0) row
    const int g       = (lane < 20) ? (sect * 20 + u) : u;

    float ns = NS_SIG, amul = 1.f, aadd = 0.f;
    if (sect == 2 && lane < 20) { ns = NS_TANH; amul = 2.f; aadd = -1.f; }  // g-gate = tanh

    float w0[HIDN], wi1[HIDN], wh1[HIDN];
    #pragma unroll
    for (int k = 0; k < HIDN; k++) {
        w0[k]  = __ldg(&W_hh0[g * HIDN + k]);
        wi1[k] = __ldg(&W_ih1[g * HIDN + k]);
        wh1[k] = __ldg(&W_hh1[g * HIDN + k]);
    }
    const float b1 = g_b1[g];

    if (tid < HIDN) {
        sh_h0[0][tid] = 0.f; sh_h0[1][tid] = 0.f;
        sh_h1[0][tid] = 0.f; sh_h1[1][tid] = 0.f;
    }
    __syncthreads();

    float c0 = 0.f, c1 = 0.f, h0r = 0.f, h1r = 0.f;
    float p0 = __ldg(&g_pre0[0 * G4 + g]);
    float p1 = __ldg(&g_pre0[1 * G4 + g]);
    float p2 = __ldg(&g_pre0[2 * G4 + g]);
    int pp = 0;

    // ---- Prologue: t = 0 (h0(-1)=0 -> gate preact = pre0 directly) ----
    {
        float pf = __ldg(&g_pre0[3 * G4 + g]);
        float act = act_sig(p0, ns, amul, aadd);
        float iv = __shfl_sync(0xFFFFFFFFu, act, u_local);
        float fv = __shfl_sync(0xFFFFFFFFu, act, u_local + 5);
        float gv = __shfl_sync(0xFFFFFFFFu, act, u_local + 10);
        float ov = __shfl_sync(0xFFFFFFFFu, act, u_local + 15);
        (void)fv;
        c0  = iv * gv;                     // c_{-1} = 0
        h0r = ov * fast_tanh(c0);
        if (lane < 5) sh_h0[1][u] = h0r;
        p0 = p1; p1 = p2; p2 = pf;
        __syncthreads();
        pp = 1;
    }

    // ---- Main loop: t = 1..TT-1. Computes h0(t) and h1(t-1), branch-free. ----
    for (int t = 1; t < TT; t++) {
        float h0p[HIDN], h1p[HIDN];
        ld20(h0p, sh_h0[pp]);              // h0(t-1)
        ld20(h1p, sh_h1[pp]);              // h1(t-2)
        float pf = (t + 3 < TT) ? __ldg(&g_pre0[(t + 3) * G4 + g]) : 0.f;

        // Layer-0 dot (4 accumulators) and Layer-1 fused 40-FMA dot (8 accs),
        // interleaved: fully independent chains.
        float a0 = p0, a1 = 0.f, a2 = 0.f, a3 = 0.f;
        float q0 = b1, q1 = 0.f, q2 = 0.f, q3 = 0.f;
        float q4 = 0.f, q5 = 0.f, q6 = 0.f, q7 = 0.f;
        #pragma unroll
        for (int k = 0; k < 5; k++) {
            a0 = fmaf(w0[k],       h0p[k],      a0);
            a1 = fmaf(w0[k + 5],   h0p[k + 5],  a1);
            a2 = fmaf(w0[k + 10],  h0p[k + 10], a2);
            a3 = fmaf(w0[k + 15],  h0p[k + 15], a3);
            q0 = fmaf(wi1[k],      h0p[k],      q0);
            q1 = fmaf(wi1[k + 5],  h0p[k + 5],  q1);
            q2 = fmaf(wi1[k + 10], h0p[k + 10], q2);
            q3 = fmaf(wi1[k + 15], h0p[k + 15], q3);
            q4 = fmaf(wh1[k],      h1p[k],      q4);
            q5 = fmaf(wh1[k + 5],  h1p[k + 5],  q5);
            q6 = fmaf(wh1[k + 10], h1p[k + 10], q6);
            q7 = fmaf(wh1[k + 15], h1p[k + 15], q7);
        }
        float a = (a0 + a1) + (a2 + a3);
        float b = ((q0 + q1) + (q2 + q3)) + ((q4 + q5) + (q6 + q7));

        float act0 = act_sig(a, ns, amul, aadd);
        float act1 = act_sig(b, ns, amul, aadd);

        float iv0 = __shfl_sync(0xFFFFFFFFu, act0, u_local);
        float fv0 = __shfl_sync(0xFFFFFFFFu, act0, u_local + 5);
        float gv0 = __shfl_sync(0xFFFFFFFFu, act0, u_local + 10);
        float ov0 = __shfl_sync(0xFFFFFFFFu, act0, u_local + 15);
        float iv1 = __shfl_sync(0xFFFFFFFFu, act1, u_local);
        float fv1 = __shfl_sync(0xFFFFFFFFu, act1, u_local + 5);
        float gv1 = __shfl_sync(0xFFFFFFFFu, act1, u_local + 10);
        float ov1 = __shfl_sync(0xFFFFFFFFu, act1, u_local + 15);

        c0  = fmaf(fv0, c0, iv0 * gv0);
        h0r = ov0 * fast_tanh(c0);
        c1  = fmaf(fv1, c1, iv1 * gv1);
        h1r = ov1 * fast_tanh(c1);

        if (lane < 5) {
            sh_h0[pp ^ 1][u] = h0r;        // publish h0(t)
            sh_h1[pp ^ 1][u] = h1r;        // publish h1(t-1)
            g_h1buf[(t - 1) * HIDN + u] = h1r;
        }
        p0 = p1; p1 = p2; p2 = pf;
        __syncthreads();                   // single barrier: flips ping-pong
        pp ^= 1;
    }

    // ---- Epilogue: t = TT -> compute h1(TT-1) only ----
    {
        float h0p[HIDN], h1p[HIDN];
        ld20(h0p, sh_h0[pp]);              // h0(TT-1)
        ld20(h1p, sh_h1[pp]);              // h1(TT-2)
        float q0 = b1, q1 = 0.f, q2 = 0.f, q3 = 0.f;
        float q4 = 0.f, q5 = 0.f, q6 = 0.f, q7 = 0.f;
        #pragma unroll
        for (int k = 0; k < 5; k++) {
            q0 = fmaf(wi1[k],      h0p[k],      q0);
            q1 = fmaf(wi1[k + 5],  h0p[k + 5],  q1);
            q2 = fmaf(wi1[k + 10], h0p[k + 10], q2);
            q3 = fmaf(wi1[k + 15], h0p[k + 15], q3);
            q4 = fmaf(wh1[k],      h1p[k],      q4);
            q5 = fmaf(wh1[k + 5],  h1p[k + 5],  q5);
            q6 = fmaf(wh1[k + 10], h1p[k + 10], q6);
            q7 = fmaf(wh1[k + 15], h1p[k + 15], q7);
        }
        float b = ((q0 + q1) + (q2 + q3)) + ((q4 + q5) + (q6 + q7));
        float act1 = act_sig(b, ns, amul, aadd);
        float iv = __shfl_sync(0xFFFFFFFFu, act1, u_local);
        float fv = __shfl_sync(0xFFFFFFFFu, act1, u_local + 5);
        float gv = __shfl_sync(0xFFFFFFFFu, act1, u_local + 10);
        float ov = __shfl_sync(0xFFFFFFFFu, act1, u_local + 15);
        c1  = fmaf(fv, c1, iv * gv);
        h1r = ov * fast_tanh(c1);
        if (lane < 5) g_h1buf[(TT - 1) * HIDN + u] = h1r;
    }

    if (lane < 5) {                        // final states: h_n then c_n
        out_tail[u]            = h0r;
        out_tail[HIDN + u]     = h1r;
        out_tail[2 * HIDN + u] = c0;
        out_tail[3 * HIDN + u] = c1;
    }
}

// ---------------------------------------------------------------------------
// Parallel output pass: out[t] = h1[t] . W_out + b_out
// ---------------------------------------------------------------------------
__global__ void out_kernel(const float* __restrict__ W_out,
                           const float* __restrict__ b_out,
                           float* __restrict__ out) {
    int t = blockIdx.x * blockDim.x + threadIdx.x;
    if (t >= TT) return;
    float wv[HIDN];
    #pragma unroll
    for (int k = 0; k < HIDN; k++) wv[k] = __ldg(&W_out[k]);
    const float4* h4 = reinterpret_cast<const float4*>(&g_h1buf[t * HIDN]);
    float acc = __ldg(b_out);
    #pragma unroll
    for (int i = 0; i < 5; i++) {
        float4 v = __ldg(&h4[i]);
        acc += wv[4 * i] * v.x + wv[4 * i + 1] * v.y
             + wv[4 * i + 2] * v.z + wv[4 * i + 3] * v.w;
    }
    out[t] = acc;
}

extern "C" void kernel_launch(void* const* d_in, const int* in_sizes, int n_in,
                              void* d_out, int out_size) {
    const float* in_states = (const float*)d_in[0];
    const float* W_inp     = (const float*)d_in[1];
    const float* b_inp     = (const float*)d_in[2];
    const float* W_ih0     = (const float*)d_in[3];
    const float* W_hh0     = (const float*)d_in[4];
    const float* b_ih0     = (const float*)d_in[5];
    const float* b_hh0     = (const float*)d_in[6];
    const float* W_ih1     = (const float*)d_in[7];
    const float* W_hh1     = (const float*)d_in[8];
    const float* b_ih1     = (const float*)d_in[9];
    const float* b_hh1     = (const float*)d_in[10];
    const float* W_out     = (const float*)d_in[11];
    const float* b_out     = (const float*)d_in[12];
    float* out = (float*)d_out;

    prep_kernel<<<1, 128>>>(W_inp, b_inp, W_ih0, b_ih0, b_hh0, b_ih1, b_hh1);
    pre0_kernel<<<TT / 4, 320>>>(in_states);
    lstm_seq_kernel<<<1, 128>>>(W_hh0, W_ih1, W_hh1, out + TT);
    out_kernel<<<(TT + 255) / 256, 256>>>(W_out, b_out, out);
}

// round 9
// speedup vs baseline: 1.3588x; 1.0153x over previous
#include <cuda_runtime.h>

#define TT 400000
#define HIDN 20
#define G4 80
#define INDIM 40

// Static device scratch (no dynamic allocation allowed).
__device__ float g_pre0[TT * G4];    // fused layer-0 pre-activations [T,80] (128 MB)
__device__ float g_h1buf[TT * HIDN]; // h1 per step for the parallel output pass (32 MB)
__device__ float g_M[G4 * INDIM];    // fused (W_ih0 @ W_inp) [80,40]
__device__ float g_b0[G4];           // fused layer-0 bias
__device__ float g_b1[G4];           // b_ih1 + b_hh1

// ---------------------------------------------------------------------------
// Prep: fuse input projection into layer-0 input matmul.
// ---------------------------------------------------------------------------
__global__ void prep_kernel(const float* __restrict__ W_inp,
                            const float* __restrict__ b_inp,
                            const float* __restrict__ W_ih0,
                            const float* __restrict__ b_ih0,
                            const float* __restrict__ b_hh0,
                            const float* __restrict__ b_ih1,
                            const float* __restrict__ b_hh1) {
    int tid = threadIdx.x;
    if (tid < G4) {
        g_b1[tid] = b_ih1[tid] + b_hh1[tid];
        float s = b_ih0[tid] + b_hh0[tid];
        #pragma unroll
        for (int e = 0; e < HIDN; e++) s += W_ih0[tid * HIDN + e] * b_inp[e];
        g_b0[tid] = s;
    }
    for (int idx = tid; idx < G4 * INDIM; idx += blockDim.x) {
        int g = idx / INDIM, k = idx % INDIM;
        float s = 0.f;
        #pragma unroll
        for (int e = 0; e < HIDN; e++) s += W_ih0[g * HIDN + e] * W_inp[e * INDIM + k];
        g_M[idx] = s;
    }
}

// ---------------------------------------------------------------------------
// Parallel pass: pre0 for all T timesteps. Block = 320 threads = 4 rows x 80 cols.
// ---------------------------------------------------------------------------
__global__ __launch_bounds__(320) void pre0_kernel(const float* __restrict__ in_states) {
    __shared__ float sM[G4 * 41];
    __shared__ float sB[G4];
    __shared__ float sIn[4 * INDIM];
    int tid = threadIdx.x;
    for (int idx = tid; idx < G4 * INDIM; idx += 320)
        sM[(idx / INDIM) * 41 + (idx % INDIM)] = g_M[idx];
    if (tid < G4) sB[tid] = g_b0[tid];
    if (tid < 4 * INDIM) sIn[tid] = in_states[blockIdx.x * 4 * INDIM + tid];
    __syncthreads();

    int r = tid / G4;
    int g = tid % G4;
    float acc = sB[g];
    #pragma unroll
    for (int k = 0; k < INDIM; k++) acc += sIn[r * INDIM + k] * sM[g * 41 + k];
    g_pre0[(blockIdx.x * 4 + r) * G4 + g] = acc;
}

// ---------------------------------------------------------------------------
// Fast activations: ex2.approx + rcp.approx (pinned via PTX).
//   sigmoid(x) = rcp(1 + ex2(-x*log2e));  tanh(x) = 2*sigmoid(2x) - 1
// ---------------------------------------------------------------------------
__device__ __forceinline__ float ex2f(float x) {
    float y; asm("ex2.approx.f32 %0, %1;" : "=f"(y) : "f"(x)); return y;
}
__device__ __forceinline__ float rcpf(float x) {
    float y; asm("rcp.approx.f32 %0, %1;" : "=f"(y) : "f"(x)); return y;
}
__device__ __forceinline__ float act_sig(float a, float ns, float mul, float add) {
    float s = rcpf(1.0f + ex2f(a * ns));
    return fmaf(s, mul, add);
}
#define NS_SIG  (-1.4426950408889634f)
#define NS_TANH (-2.8853900817779268f)
__device__ __forceinline__ float fast_tanh(float a) { return act_sig(a, NS_TANH, 2.f, -1.f); }

__device__ __forceinline__ void ld20(float* d, const float* s) {
    const float4* s4 = reinterpret_cast<const float4*>(s);
    #pragma unroll
    for (int i = 0; i < 5; i++) {
        float4 v = s4[i];
        d[4 * i] = v.x; d[4 * i + 1] = v.y; d[4 * i + 2] = v.z; d[4 * i + 3] = v.w;
    }
}

// ---------------------------------------------------------------------------
// Serial recurrence, layer-split + software-pipelined. 256 threads = 8 warps.
//   Warps 0-3  : layer 0. Warp wl owns units u = 5*wl..5*wl+4.
//   Warps 4-7  : layer 1 (computes h1(t-1) at iteration t).
//   lane = 5*sect + u_local, gate g = sect*20 + u (sect order: i,f,g,o).
//   Gate->cell exchange in-warp via SHFL; c replicated across sect lanes.
//   ONE __syncthreads per iteration; ping-pong h buffers.
//   Dependence is one-way (L1 reads L0's h0; L0 reads nothing of L1), so L0
//   warps arrive early and the barrier release is gated by the L1 path only.
// ---------------------------------------------------------------------------
__global__ __launch_bounds__(256, 1) void lstm_seq_kernel(
        const float* __restrict__ W_hh0,
        const float* __restrict__ W_ih1,
        const float* __restrict__ W_hh1,
        float* __restrict__ out_tail)   // d_out + TT : [h0(20), h1(20), c0(20), c1(20)]
{
    __shared__ __align__(16) float sh_h0[2][HIDN];  // ping-pong
    __shared__ __align__(16) float sh_h1[2][HIDN];  // ping-pong

    const int tid     = threadIdx.x;
    const int lane    = tid & 31;
    const int w       = tid >> 5;
    const bool isL0   = (w < 4);
    const int wl      = isL0 ? w : (w - 4);
    const int u_local = lane % 5;
    const int sect    = lane / 5;
    const int u       = wl * 5 + u_local;
    // lanes 20..31 compute harmless duplicates of the i-gate row
    const int g       = (lane < 20) ? (sect * 20 + u) : u;

    float ns = NS_SIG, amul = 1.f, aadd = 0.f;
    if (sect == 2 && lane < 20) { ns = NS_TANH; amul = 2.f; aadd = -1.f; }  // g-gate = tanh

    float w0[HIDN];               // L0 weights
    float wi1[HIDN], wh1[HIDN];   // L1 weights
    float b1 = 0.f;
    if (isL0) {
        #pragma unroll
        for (int k = 0; k < HIDN; k++) w0[k] = __ldg(&W_hh0[g * HIDN + k]);
    } else {
        #pragma unroll
        for (int k = 0; k < HIDN; k++) {
            wi1[k] = __ldg(&W_ih1[g * HIDN + k]);
            wh1[k] = __ldg(&W_hh1[g * HIDN + k]);
        }
        b1 = g_b1[g];
    }

    if (tid < HIDN) {
        sh_h0[0][tid] = 0.f; sh_h0[1][tid] = 0.f;
        sh_h1[0][tid] = 0.f; sh_h1[1][tid] = 0.f;
    }
    __syncthreads();

    float c0 = 0.f, c1 = 0.f, h0r = 0.f, h1r = 0.f;
    float p0 = 0.f, p1 = 0.f, p2 = 0.f;
    if (isL0) {
        p0 = __ldg(&g_pre0[0 * G4 + g]);
        p1 = __ldg(&g_pre0[1 * G4 + g]);
        p2 = __ldg(&g_pre0[2 * G4 + g]);
    }
    int pp = 0;

    // ---- Prologue: t = 0, layer 0 only (h0(-1)=0 -> preact = pre0 directly) ----
    if (isL0) {
        float pf = __ldg(&g_pre0[3 * G4 + g]);
        float act = act_sig(p0, ns, amul, aadd);
        float iv = __shfl_sync(0xFFFFFFFFu, act, u_local);
        float gv = __shfl_sync(0xFFFFFFFFu, act, u_local + 10);
        float ov = __shfl_sync(0xFFFFFFFFu, act, u_local + 15);
        c0  = iv * gv;                     // c_{-1} = 0
        h0r = ov * fast_tanh(c0);
        if (lane < 5) sh_h0[1][u] = h0r;
        p0 = p1; p1 = p2; p2 = pf;
    }
    __syncthreads();
    pp = 1;

    // ---- Main loop: t = 1..TT-1. L0 computes h0(t); L1 computes h1(t-1). ----
    for (int t = 1; t < TT; t++) {
        if (isL0) {
            float h0p[HIDN];
            ld20(h0p, sh_h0[pp]);              // h0(t-1)
            int tp = t + 3; tp = (tp < TT) ? tp : (TT - 1);
            float pf = __ldg(&g_pre0[tp * G4 + g]);

            float a0 = p0, a1 = 0.f, a2 = 0.f, a3 = 0.f;
            #pragma unroll
            for (int k = 0; k < 5; k++) {
                a0 = fmaf(w0[k],      h0p[k],      a0);
                a1 = fmaf(w0[k + 5],  h0p[k + 5],  a1);
                a2 = fmaf(w0[k + 10], h0p[k + 10], a2);
                a3 = fmaf(w0[k + 15], h0p[k + 15], a3);
            }
            float a = (a0 + a1) + (a2 + a3);
            float act = act_sig(a, ns, amul, aadd);
            float iv = __shfl_sync(0xFFFFFFFFu, act, u_local);
            float fv = __shfl_sync(0xFFFFFFFFu, act, u_local + 5);
            float gv = __shfl_sync(0xFFFFFFFFu, act, u_local + 10);
            float ov = __shfl_sync(0xFFFFFFFFu, act, u_local + 15);
            c0  = fmaf(fv, c0, iv * gv);
            h0r = ov * fast_tanh(c0);
            if (lane < 5) sh_h0[pp ^ 1][u] = h0r;   // publish h0(t)
            p0 = p1; p1 = p2; p2 = pf;
        } else {
            float h0p[HIDN], h1p[HIDN];
            ld20(h0p, sh_h0[pp]);              // h0(t-1)
            ld20(h1p, sh_h1[pp]);              // h1(t-2)

            float q0 = b1, q1 = 0.f, q2 = 0.f, q3 = 0.f;
            float q4 = 0.f, q5 = 0.f, q6 = 0.f, q7 = 0.f;
            #pragma unroll
            for (int k = 0; k < 5; k++) {
                q0 = fmaf(wi1[k],      h0p[k],      q0);
                q1 = fmaf(wi1[k + 5],  h0p[k + 5],  q1);
                q2 = fmaf(wi1[k + 10], h0p[k + 10], q2);
                q3 = fmaf(wi1[k + 15], h0p[k + 15], q3);
                q4 = fmaf(wh1[k],      h1p[k],      q4);
                q5 = fmaf(wh1[k + 5],  h1p[k + 5],  q5);
                q6 = fmaf(wh1[k + 10], h1p[k + 10], q6);
                q7 = fmaf(wh1[k + 15], h1p[k + 15], q7);
            }
            float b = ((q0 + q1) + (q2 + q3)) + ((q4 + q5) + (q6 + q7));
            float act = act_sig(b, ns, amul, aadd);
            float iv = __shfl_sync(0xFFFFFFFFu, act, u_local);
            float fv = __shfl_sync(0xFFFFFFFFu, act, u_local + 5);
            float gv = __shfl_sync(0xFFFFFFFFu, act, u_local + 10);
            float ov = __shfl_sync(0xFFFFFFFFu, act, u_local + 15);
            c1  = fmaf(fv, c1, iv * gv);
            h1r = ov * fast_tanh(c1);
            if (lane < 5) {
                sh_h1[pp ^ 1][u] = h1r;            // publish h1(t-1)
                g_h1buf[(t - 1) * HIDN + u] = h1r;
            }
        }
        __syncthreads();                   // single barrier: flips ping-pong
        pp ^= 1;
    }

    // ---- Epilogue: t = TT -> L1 computes h1(TT-1) ----
    if (!isL0) {
        float h0p[HIDN], h1p[HIDN];
        ld20(h0p, sh_h0[pp]);              // h0(TT-1)
        ld20(h1p, sh_h1[pp]);              // h1(TT-2)
        float q0 = b1, q1 = 0.f, q2 = 0.f, q3 = 0.f;
        float q4 = 0.f, q5 = 0.f, q6 = 0.f, q7 = 0.f;
        #pragma unroll
        for (int k = 0; k < 5; k++) {
            q0 = fmaf(wi1[k],      h0p[k],      q0);
            q1 = fmaf(wi1[k + 5],  h0p[k + 5],  q1);
            q2 = fmaf(wi1[k + 10], h0p[k + 10], q2);
            q3 = fmaf(wi1[k + 15], h0p[k + 15], q3);
            q4 = fmaf(wh1[k],      h1p[k],      q4);
            q5 = fmaf(wh1[k + 5],  h1p[k + 5],  q5);
            q6 = fmaf(wh1[k + 10], h1p[k + 10], q6);
            q7 = fmaf(wh1[k + 15], h1p[k + 15], q7);
        }
        float b = ((q0 + q1) + (q2 + q3)) + ((q4 + q5) + (q6 + q7));
        float act = act_sig(b, ns, amul, aadd);
        float iv = __shfl_sync(0xFFFFFFFFu, act, u_local);
        float fv = __shfl_sync(0xFFFFFFFFu, act, u_local + 5);
        float gv = __shfl_sync(0xFFFFFFFFu, act, u_local + 10);
        float ov = __shfl_sync(0xFFFFFFFFu, act, u_local + 15);
        c1  = fmaf(fv, c1, iv * gv);
        h1r = ov * fast_tanh(c1);
        if (lane < 5) {
            g_h1buf[(TT - 1) * HIDN + u] = h1r;
            out_tail[HIDN + u]     = h1r;          // h_n layer 1
            out_tail[3 * HIDN + u] = c1;           // c_n layer 1
        }
    } else if (lane < 5) {
        out_tail[u]            = h0r;              // h_n layer 0
        out_tail[2 * HIDN + u] = c0;               // c_n layer 0
    }
}

// ---------------------------------------------------------------------------
// Parallel output pass: out[t] = h1[t] . W_out + b_out
// ---------------------------------------------------------------------------
__global__ void out_kernel(const float* __restrict__ W_out,
                           const float* __restrict__ b_out,
                           float* __restrict__ out) {
    int t = blockIdx.x * blockDim.x + threadIdx.x;
    if (t >= TT) return;
    float wv[HIDN];
    #pragma unroll
    for (int k = 0; k < HIDN; k++) wv[k] = __ldg(&W_out[k]);
    const float4* h4 = reinterpret_cast<const float4*>(&g_h1buf[t * HIDN]);
    float acc = __ldg(b_out);
    #pragma unroll
    for (int i = 0; i < 5; i++) {
        float4 v = __ldg(&h4[i]);
        acc += wv[4 * i] * v.x + wv[4 * i + 1] * v.y
             + wv[4 * i + 2] * v.z + wv[4 * i + 3] * v.w;
    }
    out[t] = acc;
}

extern "C" void kernel_launch(void* const* d_in, const int* in_sizes, int n_in,
                              void* d_out, int out_size) {
    const float* in_states = (const float*)d_in[0];
    const float* W_inp     = (const float*)d_in[1];
    const float* b_inp     = (const float*)d_in[2];
    const float* W_ih0     = (const float*)d_in[3];
    const float* W_hh0     = (const float*)d_in[4];
    const float* b_ih0     = (const float*)d_in[5];
    const float* b_hh0     = (const float*)d_in[6];
    const float* W_ih1     = (const float*)d_in[7];
    const float* W_hh1     = (const float*)d_in[8];
    const float* b_ih1     = (const float*)d_in[9];
    const float* b_hh1     = (const float*)d_in[10];
    const float* W_out     = (const float*)d_in[11];
    const float* b_out     = (const float*)d_in[12];
    float* out = (float*)d_out;

    prep_kernel<<<1, 128>>>(W_inp, b_inp, W_ih0, b_ih0, b_hh0, b_ih1, b_hh1);
    pre0_kernel<<<TT / 4, 320>>>(in_states);
    lstm_seq_kernel<<<1, 256>>>(W_hh0, W_ih1, W_hh1, out + TT);
    out_kernel<<<(TT + 255) / 256, 256>>>(W_out, b_out, out);
}

// round 11
// speedup vs baseline: 1.9727x; 1.4518x over previous
#include <cuda_runtime.h>

#define TT 400000
#define HIDN 20
#define G4 80
#define INDIM 40

typedef unsigned int u32;

// Static device scratch (no dynamic allocation allowed).
__device__ float g_pre0[TT * G4];    // fused layer-0 pre-activations [T,80] (128 MB)
__device__ float g_h1buf[TT * HIDN]; // h1 per step for the parallel output pass (32 MB)
__device__ float g_M[G4 * INDIM];    // fused (W_ih0 @ W_inp) [80,40]
__device__ float g_b0[G4];           // fused layer-0 bias
__device__ float g_b1[G4];           // b_ih1 + b_hh1

// ---------------------------------------------------------------------------
// Prep: fuse input projection into layer-0 input matmul.
// ---------------------------------------------------------------------------
__global__ void prep_kernel(const float* __restrict__ W_inp,
                            const float* __restrict__ b_inp,
                            const float* __restrict__ W_ih0,
                            const float* __restrict__ b_ih0,
                            const float* __restrict__ b_hh0,
                            const float* __restrict__ b_ih1,
                            const float* __restrict__ b_hh1) {
    int tid = threadIdx.x;
    if (tid < G4) {
        g_b1[tid] = b_ih1[tid] + b_hh1[tid];
        float s = b_ih0[tid] + b_hh0[tid];
        #pragma unroll
        for (int e = 0; e < HIDN; e++) s += W_ih0[tid * HIDN + e] * b_inp[e];
        g_b0[tid] = s;
    }
    for (int idx = tid; idx < G4 * INDIM; idx += blockDim.x) {
        int g = idx / INDIM, k = idx % INDIM;
        float s = 0.f;
        #pragma unroll
        for (int e = 0; e < HIDN; e++) s += W_ih0[g * HIDN + e] * W_inp[e * INDIM + k];
        g_M[idx] = s;
    }
}

// ---------------------------------------------------------------------------
// Parallel pass: pre0 for all T timesteps. Block = 320 threads = 4 rows x 80 cols.
// ---------------------------------------------------------------------------
__global__ __launch_bounds__(320) void pre0_kernel(const float* __restrict__ in_states) {
    __shared__ float sM[G4 * 41];
    __shared__ float sB[G4];
    __shared__ float sIn[4 * INDIM];
    int tid = threadIdx.x;
    for (int idx = tid; idx < G4 * INDIM; idx += 320)
        sM[(idx / INDIM) * 41 + (idx % INDIM)] = g_M[idx];
    if (tid < G4) sB[tid] = g_b0[tid];
    if (tid < 4 * INDIM) sIn[tid] = in_states[blockIdx.x * 4 * INDIM + tid];
    __syncthreads();

    int r = tid / G4;
    int g = tid % G4;
    float acc = sB[g];
    #pragma unroll
    for (int k = 0; k < INDIM; k++) acc += sIn[r * INDIM + k] * sM[g * 41 + k];
    g_pre0[(blockIdx.x * 4 + r) * G4 + g] = acc;
}

// ---------------------------------------------------------------------------
// Fast activations: ex2.approx + rcp.approx (pinned via PTX).
//   sigmoid(x) = rcp(1 + ex2(-x*log2e));  tanh(x) = 2*sigmoid(2x) - 1
// ---------------------------------------------------------------------------
__device__ __forceinline__ float ex2f(float x) {
    float y; asm("ex2.approx.f32 %0, %1;" : "=f"(y) : "f"(x)); return y;
}
__device__ __forceinline__ float rcpf(float x) {
    float y; asm("rcp.approx.f32 %0, %1;" : "=f"(y) : "f"(x)); return y;
}
__device__ __forceinline__ float act_sig(float a, float ns, float mul, float add) {
    float s = rcpf(1.0f + ex2f(a * ns));
    return fmaf(s, mul, add);
}
#define NS_SIG  (-1.4426950408889634f)
#define NS_TANH (-2.8853900817779268f)
__device__ __forceinline__ float fast_tanh(float a) { return act_sig(a, NS_TANH, 2.f, -1.f); }

__device__ __forceinline__ void ld20(float* d, const float* s) {
    const float4* s4 = reinterpret_cast<const float4*>(s);
    #pragma unroll
    for (int i = 0; i < 5; i++) {
        float4 v = s4[i];
        d[4 * i] = v.x; d[4 * i + 1] = v.y; d[4 * i + 2] = v.z; d[4 * i + 3] = v.w;
    }
}

__device__ __forceinline__ u32 smem_u32(const void* p) {
    return (u32)__cvta_generic_to_shared(p);
}
// Predicated 4-byte async copy gmem -> smem (LDGSTS; no register, no SB wait).
__device__ __forceinline__ void cp_async4(u32 dst, const float* src, int pred) {
    asm volatile(
        "{\n\t.reg .pred p;\n\tsetp.ne.u32 p, %2, 0;\n\t"
        "@p cp.async.ca.shared.global [%0], [%1], 4;\n\t}"
        :: "r"(dst), "l"(src), "r"(pred));
}

#define PF_DIST 6   // prefetch distance (iterations); ring has 8 slots

// ---------------------------------------------------------------------------
// Serial recurrence, layer-split + software-pipelined. 256 threads = 8 warps.
//   Warps 0-3 : layer 0 (h0(t)).  Warps 4-7 : layer 1 (h1(t-1)).
//   lane = 5*sect + u_local, gate g = sect*20 + u (sect order: i,f,g,o).
//   pre0 delivered via per-lane cp.async ring (8 slots, 6-deep pipeline):
//   each lane fetches ONLY the value it consumes -> same-thread wait_group,
//   no cross-thread ordering needed, zero exposed DRAM latency.
//   ONE __syncthreads per iteration; ping-pong h buffers.
// ---------------------------------------------------------------------------
__global__ __launch_bounds__(256, 1) void lstm_seq_kernel(
        const float* __restrict__ W_hh0,
        const float* __restrict__ W_ih1,
        const float* __restrict__ W_hh1,
        float* __restrict__ out_tail)   // d_out + TT : [h0(20), h1(20), c0(20), c1(20)]
{
    __shared__ __align__(16) float sh_h0[2][HIDN];   // ping-pong
    __shared__ __align__(16) float sh_h1[2][HIDN];   // ping-pong
    __shared__ __align__(16) float sh_pre[8][G4];    // pre0 ring (8 slots)

    const int tid     = threadIdx.x;
    const int lane    = tid & 31;
    const int w       = tid >> 5;
    const bool isL0   = (w < 4);
    const int wl      = isL0 ? w : (w - 4);
    const int u_local = lane % 5;
    const int sect    = lane / 5;
    const int u       = wl * 5 + u_local;
    const int g       = (lane < 20) ? (sect * 20 + u) : u;   // lanes 20..31: dupes

    float ns = NS_SIG, amul = 1.f, aadd = 0.f;
    if (sect == 2 && lane < 20) { ns = NS_TANH; amul = 2.f; aadd = -1.f; }  // g-gate

    float w0[HIDN];               // L0 weights
    float wi1[HIDN], wh1[HIDN];   // L1 weights
    float b1 = 0.f;
    if (isL0) {
        #pragma unroll
        for (int k = 0; k < HIDN; k++) w0[k] = __ldg(&W_hh0[g * HIDN + k]);
    } else {
        #pragma unroll
        for (int k = 0; k < HIDN; k++) {
            wi1[k] = __ldg(&W_ih1[g * HIDN + k]);
            wh1[k] = __ldg(&W_hh1[g * HIDN + k]);
        }
        b1 = g_b1[g];
    }

    const u32 spre = smem_u32(&sh_pre[0][0]);
    const int do_cp = isL0 && (lane < 20);

    // Pipeline prologue: queue pre0 for steps 1..PF_DIST (one group per step).
    if (isL0) {
        #pragma unroll
        for (int j = 1; j <= PF_DIST; j++) {
            cp_async4(spre + (u32)(((j & 7) * G4 + g) * 4),
                      &g_pre0[j * G4 + g], do_cp);
            asm volatile("cp.async.commit_group;");
        }
    }

    if (tid < HIDN) {
        sh_h0[0][tid] = 0.f; sh_h0[1][tid] = 0.f;
        sh_h1[0][tid] = 0.f; sh_h1[1][tid] = 0.f;
    }
    __syncthreads();

    float c0 = 0.f, c1 = 0.f, h0r = 0.f, h1r = 0.f;
    int pp = 0;

    // ---- Prologue: t = 0, layer 0 only (h0(-1)=0 -> preact = pre0 directly) ----
    if (isL0) {
        float p = __ldg(&g_pre0[0 * G4 + g]);
        float act = act_sig(p, ns, amul, aadd);
        float iv = __shfl_sync(0xFFFFFFFFu, act, u_local);
        float gv = __shfl_sync(0xFFFFFFFFu, act, u_local + 10);
        float ov = __shfl_sync(0xFFFFFFFFu, act, u_local + 15);
        c0  = iv * gv;                     // c_{-1} = 0
        h0r = ov * fast_tanh(c0);
        if (lane < 5) sh_h0[1][u] = h0r;
    }
    __syncthreads();
    pp = 1;

    // ---- Main loop: t = 1..TT-1. L0 computes h0(t); L1 computes h1(t-1). ----
    for (int t = 1; t < TT; t++) {
        if (isL0) {
            // Queue step t+PF_DIST (slot differs from slot t by 6 mod 8; that
            // slot was last read 2 barriers ago -> safe to overwrite).
            int tp = t + PF_DIST;
            cp_async4(spre + (u32)(((tp & 7) * G4 + g) * 4),
                      &g_pre0[tp * G4 + g], do_cp & (tp < TT));
            asm volatile("cp.async.commit_group;");

            float h0p[HIDN];
            ld20(h0p, sh_h0[pp]);              // h0(t-1)

            // Oldest of the 7 outstanding groups is step t -> wait it down.
            asm volatile("cp.async.wait_group 6;");
            float a0 = sh_pre[t & 7][g];
            float a1 = 0.f, a2 = 0.f, a3 = 0.f;
            #pragma unroll
            for (int k = 0; k < 5; k++) {
                a0 = fmaf(w0[k],      h0p[k],      a0);
                a1 = fmaf(w0[k + 5],  h0p[k + 5],  a1);
                a2 = fmaf(w0[k + 10], h0p[k + 10], a2);
                a3 = fmaf(w0[k + 15], h0p[k + 15], a3);
            }
            float a = (a0 + a1) + (a2 + a3);
            float act = act_sig(a, ns, amul, aadd);
            float iv = __shfl_sync(0xFFFFFFFFu, act, u_local);
            float fv = __shfl_sync(0xFFFFFFFFu, act, u_local + 5);
            float gv = __shfl_sync(0xFFFFFFFFu, act, u_local + 10);
            float ov = __shfl_sync(0xFFFFFFFFu, act, u_local + 15);
            c0  = fmaf(fv, c0, iv * gv);
            h0r = ov * fast_tanh(c0);
            if (lane < 5) sh_h0[pp ^ 1][u] = h0r;   // publish h0(t)
        } else {
            float h0p[HIDN], h1p[HIDN];
            ld20(h0p, sh_h0[pp]);              // h0(t-1)
            ld20(h1p, sh_h1[pp]);              // h1(t-2)

            float q0 = b1, q1 = 0.f, q2 = 0.f, q3 = 0.f;
            float q4 = 0.f, q5 = 0.f, q6 = 0.f, q7 = 0.f;
            #pragma unroll
            for (int k = 0; k < 5; k++) {
                q0 = fmaf(wi1[k],      h0p[k],      q0);
                q1 = fmaf(wi1[k + 5],  h0p[k + 5],  q1);
                q2 = fmaf(wi1[k + 10], h0p[k + 10], q2);
                q3 = fmaf(wi1[k + 15], h0p[k + 15], q3);
                q4 = fmaf(wh1[k],      h1p[k],      q4);
                q5 = fmaf(wh1[k + 5],  h1p[k + 5],  q5);
                q6 = fmaf(wh1[k + 10], h1p[k + 10], q6);
                q7 = fmaf(wh1[k + 15], h1p[k + 15], q7);
            }
            float b = ((q0 + q1) + (q2 + q3)) + ((q4 + q5) + (q6 + q7));
            float act = act_sig(b, ns, amul, aadd);
            float iv = __shfl_sync(0xFFFFFFFFu, act, u_local);
            float fv = __shfl_sync(0xFFFFFFFFu, act, u_local + 5);
            float gv = __shfl_sync(0xFFFFFFFFu, act, u_local + 10);
            float ov = __shfl_sync(0xFFFFFFFFu, act, u_local + 15);
            c1  = fmaf(fv, c1, iv * gv);
            h1r = ov * fast_tanh(c1);
            if (lane < 5) {
                sh_h1[pp ^ 1][u] = h1r;            // publish h1(t-1)
                g_h1buf[(t - 1) * HIDN + u] = h1r;
            }
        }
        __syncthreads();                   // single barrier: flips ping-pong
        pp ^= 1;
    }

    // ---- Epilogue: t = TT -> L1 computes h1(TT-1) ----
    if (!isL0) {
        float h0p[HIDN], h1p[HIDN];
        ld20(h0p, sh_h0[pp]);              // h0(TT-1)
        ld20(h1p, sh_h1[pp]);              // h1(TT-2)
        float q0 = b1, q1 = 0.f, q2 = 0.f, q3 = 0.f;
        float q4 = 0.f, q5 = 0.f, q6 = 0.f, q7 = 0.f;
        #pragma unroll
        for (int k = 0; k < 5; k++) {
            q0 = fmaf(wi1[k],      h0p[k],      q0);
            q1 = fmaf(wi1[k + 5],  h0p[k + 5],  q1);
            q2 = fmaf(wi1[k + 10], h0p[k + 10], q2);
            q3 = fmaf(wi1[k + 15], h0p[k + 15], q3);
            q4 = fmaf(wh1[k],      h1p[k],      q4);
            q5 = fmaf(wh1[k + 5],  h1p[k + 5],  q5);
            q6 = fmaf(wh1[k + 10], h1p[k + 10], q6);
            q7 = fmaf(wh1[k + 15], h1p[k + 15], q7);
        }
        float b = ((q0 + q1) + (q2 + q3)) + ((q4 + q5) + (q6 + q7));
        float act = act_sig(b, ns, amul, aadd);
        float iv = __shfl_sync(0xFFFFFFFFu, act, u_local);
        float fv = __shfl_sync(0xFFFFFFFFu, act, u_local + 5);
        float gv = __shfl_sync(0xFFFFFFFFu, act, u_local + 10);
        float ov = __shfl_sync(0xFFFFFFFFu, act, u_local + 15);
        c1  = fmaf(fv, c1, iv * gv);
        h1r = ov * fast_tanh(c1);
        if (lane < 5) {
            g_h1buf[(TT - 1) * HIDN + u] = h1r;
            out_tail[HIDN + u]     = h1r;          // h_n layer 1
            out_tail[3 * HIDN + u] = c1;           // c_n layer 1
        }
    } else if (lane < 5) {
        out_tail[u]            = h0r;              // h_n layer 0
        out_tail[2 * HIDN + u] = c0;               // c_n layer 0
    }
}

// ---------------------------------------------------------------------------
// Parallel output pass: out[t] = h1[t] . W_out + b_out
// ---------------------------------------------------------------------------
__global__ void out_kernel(const float* __restrict__ W_out,
                           const float* __restrict__ b_out,
                           float* __restrict__ out) {
    int t = blockIdx.x * blockDim.x + threadIdx.x;
    if (t >= TT) return;
    float wv[HIDN];
    #pragma unroll
    for (int k = 0; k < HIDN; k++) wv[k] = __ldg(&W_out[k]);
    const float4* h4 = reinterpret_cast<const float4*>(&g_h1buf[t * HIDN]);
    float acc = __ldg(b_out);
    #pragma unroll
    for (int i = 0; i < 5; i++) {
        float4 v = __ldg(&h4[i]);
        acc += wv[4 * i] * v.x + wv[4 * i + 1] * v.y
             + wv[4 * i + 2] * v.z + wv[4 * i + 3] * v.w;
    }
    out[t] = acc;
}

extern "C" void kernel_launch(void* const* d_in, const int* in_sizes, int n_in,
                              void* d_out, int out_size) {
    const float* in_states = (const float*)d_in[0];
    const float* W_inp     = (const float*)d_in[1];
    const float* b_inp     = (const float*)d_in[2];
    const float* W_ih0     = (const float*)d_in[3];
    const float* W_hh0     = (const float*)d_in[4];
    const float* b_ih0     = (const float*)d_in[5];
    const float* b_hh0     = (const float*)d_in[6];
    const float* W_ih1     = (const float*)d_in[7];
    const float* W_hh1     = (const float*)d_in[8];
    const float* b_ih1     = (const float*)d_in[9];
    const float* b_hh1     = (const float*)d_in[10];
    const float* W_out     = (const float*)d_in[11];
    const float* b_out     = (const float*)d_in[12];
    float* out = (float*)d_out;

    prep_kernel<<<1, 128>>>(W_inp, b_inp, W_ih0, b_ih0, b_hh0, b_ih1, b_hh1);
    pre0_kernel<<<TT / 4, 320>>>(in_states);
    lstm_seq_kernel<<<1, 256>>>(W_hh0, W_ih1, W_hh1, out + TT);
    out_kernel<<<(TT + 255) / 256, 256>>>(W_out, b_out, out);
}

// round 12
// speedup vs baseline: 2.1534x; 1.0916x over previous
#include <cuda_runtime.h>

#define TT 400000
#define HIDN 20
#define G4 80
#define INDIM 40

typedef unsigned int u32;
typedef unsigned long long u64;

// Static device scratch (no dynamic allocation allowed).
__device__ float g_pre0[TT * G4];    // fused layer-0 pre-activations [T,80] (128 MB)
__device__ float g_h1buf[TT * HIDN]; // h1 per step for the parallel output pass (32 MB)
__device__ float g_M[G4 * INDIM];    // fused (W_ih0 @ W_inp) [80,40]
__device__ float g_b0[G4];           // fused layer-0 bias
__device__ float g_b1[G4];           // b_ih1 + b_hh1

// ---------------------------------------------------------------------------
// Prep: fuse input projection into layer-0 input matmul.
// ---------------------------------------------------------------------------
__global__ void prep_kernel(const float* __restrict__ W_inp,
                            const float* __restrict__ b_inp,
                            const float* __restrict__ W_ih0,
                            const float* __restrict__ b_ih0,
                            const float* __restrict__ b_hh0,
                            const float* __restrict__ b_ih1,
                            const float* __restrict__ b_hh1) {
    int tid = threadIdx.x;
    if (tid < G4) {
        g_b1[tid] = b_ih1[tid] + b_hh1[tid];
        float s = b_ih0[tid] + b_hh0[tid];
        #pragma unroll
        for (int e = 0; e < HIDN; e++) s += W_ih0[tid * HIDN + e] * b_inp[e];
        g_b0[tid] = s;
    }
    for (int idx = tid; idx < G4 * INDIM; idx += blockDim.x) {
        int g = idx / INDIM, k = idx % INDIM;
        float s = 0.f;
        #pragma unroll
        for (int e = 0; e < HIDN; e++) s += W_ih0[g * HIDN + e] * W_inp[e * INDIM + k];
        g_M[idx] = s;
    }
}

// ---------------------------------------------------------------------------
// Parallel pass: pre0 for all T timesteps. Block = 320 threads = 4 rows x 80 cols.
// ---------------------------------------------------------------------------
__global__ __launch_bounds__(320) void pre0_kernel(const float* __restrict__ in_states) {
    __shared__ float sM[G4 * 41];
    __shared__ float sB[G4];
    __shared__ float sIn[4 * INDIM];
    int tid = threadIdx.x;
    for (int idx = tid; idx < G4 * INDIM; idx += 320)
        sM[(idx / INDIM) * 41 + (idx % INDIM)] = g_M[idx];
    if (tid < G4) sB[tid] = g_b0[tid];
    if (tid < 4 * INDIM) sIn[tid] = in_states[blockIdx.x * 4 * INDIM + tid];
    __syncthreads();

    int r = tid / G4;
    int g = tid % G4;
    float acc = sB[g];
    #pragma unroll
    for (int k = 0; k < INDIM; k++) acc += sIn[r * INDIM + k] * sM[g * 41 + k];
    g_pre0[(blockIdx.x * 4 + r) * G4 + g] = acc;
}

// ---------------------------------------------------------------------------
// Fast activations: ex2.approx + rcp.approx (pinned via PTX).
//   sigmoid(x) = rcp(1 + ex2(-x*log2e));  tanh(x) = 2*sigmoid(2x) - 1
// ---------------------------------------------------------------------------
__device__ __forceinline__ float ex2f(float x) {
    float y; asm("ex2.approx.f32 %0, %1;" : "=f"(y) : "f"(x)); return y;
}
__device__ __forceinline__ float rcpf(float x) {
    float y; asm("rcp.approx.f32 %0, %1;" : "=f"(y) : "f"(x)); return y;
}
__device__ __forceinline__ float act_sig(float a, float ns, float mul, float add) {
    float s = rcpf(1.0f + ex2f(a * ns));
    return fmaf(s, mul, add);
}
#define NS_SIG  (-1.4426950408889634f)
#define NS_TANH (-2.8853900817779268f)
__device__ __forceinline__ float fast_tanh(float a) { return act_sig(a, NS_TANH, 2.f, -1.f); }

// ---- Packed f32x2 helpers (Blackwell FFMA2; only reachable via PTX) ----
__device__ __forceinline__ u64 ffma2(u64 a, u64 b, u64 c) {
    u64 d; asm("fma.rn.f32x2 %0, %1, %2, %3;" : "=l"(d) : "l"(a), "l"(b), "l"(c));
    return d;
}
__device__ __forceinline__ u64 pack2(float lo, float hi) {
    u64 d; asm("mov.b64 %0, {%1, %2};" : "=l"(d) : "f"(lo), "f"(hi)); return d;
}
__device__ __forceinline__ void unpack2(u64 v, float& lo, float& hi) {
    asm("mov.b64 {%0, %1}, %2;" : "=f"(lo), "=f"(hi) : "l"(v));
}
// Load 20 floats (one h row, 16B-aligned) as 10 packed f32x2 values.
__device__ __forceinline__ void ld20p(u64* d, const float* s) {
    const ulonglong2* s2 = reinterpret_cast<const ulonglong2*>(s);
    #pragma unroll
    for (int i = 0; i < 5; i++) { ulonglong2 v = s2[i]; d[2 * i] = v.x; d[2 * i + 1] = v.y; }
}

__device__ __forceinline__ u32 smem_u32(const void* p) {
    return (u32)__cvta_generic_to_shared(p);
}
// Predicated 4-byte async copy gmem -> smem (LDGSTS; no register, no SB wait).
__device__ __forceinline__ void cp_async4(u32 dst, const float* src, int pred) {
    asm volatile(
        "{\n\t.reg .pred p;\n\tsetp.ne.u32 p, %2, 0;\n\t"
        "@p cp.async.ca.shared.global [%0], [%1], 4;\n\t}"
        :: "r"(dst), "l"(src), "r"(pred));
}

#define PF_DIST 6     // cp.async prefetch distance; pre ring has 8 slots
#define H0_RING 8     // h0 ring slots

#define BAR_L0() asm volatile("bar.sync 1, 128;" ::: "memory")
#define BAR_L1() asm volatile("bar.sync 2, 128;" ::: "memory")
#define COMPILER_FENCE() asm volatile("" ::: "memory")

// ---------------------------------------------------------------------------
// Serial recurrence: DECOUPLED layer groups, no block-wide barrier.
//   Warps 0-3 (L0): compute h0(t) into an 8-slot ring; private bar.sync 1.
//   Warps 4-7 (L1): compute h1(t-1) from ring slot t-1;  private bar.sync 2.
//   Handshake: volatile progress counters published AFTER each group barrier
//   (barrier drains STS -> counter store is a correct release). L1 spin-waits
//   prog0 >= t-1 (cached; L0 runs ahead so ~free). L0 back-pressures on
//   prog1 >= t-7 with __nanosleep backoff (don't steal issue from L1 warps).
//   Dots use packed f32x2 FFMA2; pre0 via per-lane cp.async ring (R11).
// ---------------------------------------------------------------------------
__global__ __launch_bounds__(256, 1) void lstm_seq_kernel(
        const float* __restrict__ W_hh0,
        const float* __restrict__ W_ih1,
        const float* __restrict__ W_hh1,
        float* __restrict__ out_tail)   // d_out + TT : [h0(20), h1(20), c0(20), c1(20)]
{
    __shared__ __align__(16) float sh_h0[H0_RING][HIDN];  // h0(s) in slot s&7
    __shared__ __align__(16) float sh_h1[2][HIDN];        // h1(s) in slot s&1
    __shared__ __align__(16) float sh_pre[8][G4];         // pre0 cp.async ring
    __shared__ int s_prog[2];                              // [0]=L0 step, [1]=L1 step

    const int tid     = threadIdx.x;
    const int lane    = tid & 31;
    const int w       = tid >> 5;
    const bool isL0   = (w < 4);
    const int wl      = isL0 ? w : (w - 4);
    const int u_local = lane % 5;
    const int sect    = lane / 5;
    const int u       = wl * 5 + u_local;
    const int g       = (lane < 20) ? (sect * 20 + u) : u;   // lanes 20..31: dupes

    float ns = NS_SIG, amul = 1.f, aadd = 0.f;
    if (sect == 2 && lane < 20) { ns = NS_TANH; amul = 2.f; aadd = -1.f; }  // g-gate

    // Packed weights (f32x2 pairs along k).
    u64 w0p[10], wi1p[10], wh1p[10];
    float b1 = 0.f;
    if (isL0) {
        #pragma unroll
        for (int j = 0; j < 10; j++)
            w0p[j] = pack2(__ldg(&W_hh0[g * HIDN + 2 * j]), __ldg(&W_hh0[g * HIDN + 2 * j + 1]));
    } else {
        #pragma unroll
        for (int j = 0; j < 10; j++) {
            wi1p[j] = pack2(__ldg(&W_ih1[g * HIDN + 2 * j]), __ldg(&W_ih1[g * HIDN + 2 * j + 1]));
            wh1p[j] = pack2(__ldg(&W_hh1[g * HIDN + 2 * j]), __ldg(&W_hh1[g * HIDN + 2 * j + 1]));
        }
        b1 = g_b1[g];
    }

    const u32 spre = smem_u32(&sh_pre[0][0]);
    const int do_cp = isL0 && (lane < 20);

    // cp.async pipeline prologue: queue pre0 for steps 1..PF_DIST.
    if (isL0) {
        #pragma unroll
        for (int j = 1; j <= PF_DIST; j++) {
            cp_async4(spre + (u32)(((j & 7) * G4 + g) * 4),
                      &g_pre0[j * G4 + g], do_cp);
            asm volatile("cp.async.commit_group;");
        }
    }

    if (tid < HIDN) { sh_h1[0][tid] = 0.f; sh_h1[1][tid] = 0.f; }
    if (tid == 0) { s_prog[0] = -1; s_prog[1] = 0; }
    __syncthreads();   // one full barrier: init visible to both groups

    volatile int* vprog0 = &s_prog[0];
    volatile int* vprog1 = &s_prog[1];

    if (isL0) {
        // ================= Layer-0 producer group =================
        float c0 = 0.f, h0r = 0.f;
        int cprog1 = 0;

        // t = 0: h0(-1)=0 -> preact = pre0 directly.
        {
            float p = __ldg(&g_pre0[0 * G4 + g]);
            float act = act_sig(p, ns, amul, aadd);
            float iv = __shfl_sync(0xFFFFFFFFu, act, u_local);
            float gv = __shfl_sync(0xFFFFFFFFu, act, u_local + 10);
            float ov = __shfl_sync(0xFFFFFFFFu, act, u_local + 15);
            c0  = iv * gv;
            h0r = ov * fast_tanh(c0);
            if (lane < 5) sh_h0[0][u] = h0r;
            BAR_L0();
            if (tid == 0) *vprog0 = 0;
        }

        for (int t = 1; t < TT; t++) {
            // Back-pressure: slot t&7 is read by L1 at its iteration t-7.
            if (cprog1 < t - 7) {
                cprog1 = *vprog1;
                while (cprog1 < t - 7) { __nanosleep(32); cprog1 = *vprog1; }
            }
            COMPILER_FENCE();

            // Queue pre0 for step t+PF_DIST (slot reuse distance 6 mod 8).
            int tp = t + PF_DIST;
            cp_async4(spre + (u32)(((tp & 7) * G4 + g) * 4),
                      &g_pre0[tp * G4 + g], do_cp & (tp < TT));
            asm volatile("cp.async.commit_group;");

            u64 h0p[10];
            ld20p(h0p, sh_h0[(t - 1) & 7]);    // h0(t-1)

            asm volatile("cp.async.wait_group 6;");
            float p = sh_pre[t & 7][g];

            u64 a0 = pack2(p, 0.f), a1 = 0ULL;
            #pragma unroll
            for (int j = 0; j < 5; j++) {
                a0 = ffma2(w0p[2 * j],     h0p[2 * j],     a0);
                a1 = ffma2(w0p[2 * j + 1], h0p[2 * j + 1], a1);
            }
            float x0, x1, x2, x3;
            unpack2(a0, x0, x1); unpack2(a1, x2, x3);
            float a = (x0 + x1) + (x2 + x3);

            float act = act_sig(a, ns, amul, aadd);
            float iv = __shfl_sync(0xFFFFFFFFu, act, u_local);
            float fv = __shfl_sync(0xFFFFFFFFu, act, u_local + 5);
            float gv = __shfl_sync(0xFFFFFFFFu, act, u_local + 10);
            float ov = __shfl_sync(0xFFFFFFFFu, act, u_local + 15);
            c0  = fmaf(fv, c0, iv * gv);
            h0r = ov * fast_tanh(c0);
            if (lane < 5) sh_h0[t & 7][u] = h0r;   // publish h0(t)
            BAR_L0();                               // group barrier (drains STS)
            if (tid == 0) *vprog0 = t;              // release
        }

        if (lane < 5) {                            // final states layer 0
            out_tail[u]            = h0r;
            out_tail[2 * HIDN + u] = c0;
        }
    } else {
        // ================= Layer-1 consumer group =================
        float c1 = 0.f, h1r = 0.f;
        int cprog0 = -1;

        for (int t = 1; t < TT; t++) {
            // Need h0(t-1): wait until L0 published step t-1 (cached check).
            if (cprog0 < t - 1) {
                cprog0 = *vprog0;
                while (cprog0 < t - 1) { __nanosleep(16); cprog0 = *vprog0; }
            }
            COMPILER_FENCE();

            u64 h0p[10], h1p[10];
            ld20p(h0p, sh_h0[(t - 1) & 7]);    // h0(t-1)
            ld20p(h1p, sh_h1[t & 1]);          // h1(t-2)

            u64 q0 = pack2(b1, 0.f), q1 = 0ULL, q2 = 0ULL, q3 = 0ULL;
            #pragma unroll
            for (int j = 0; j < 5; j++) {
                q0 = ffma2(wi1p[2 * j],     h0p[2 * j],     q0);
                q1 = ffma2(wi1p[2 * j + 1], h0p[2 * j + 1], q1);
                q2 = ffma2(wh1p[2 * j],     h1p[2 * j],     q2);
                q3 = ffma2(wh1p[2 * j + 1], h1p[2 * j + 1], q3);
            }
            float y0, y1, y2, y3, y4, y5, y6, y7;
            unpack2(q0, y0, y1); unpack2(q1, y2, y3);
            unpack2(q2, y4, y5); unpack2(q3, y6, y7);
            float b = ((y0 + y1) + (y2 + y3)) + ((y4 + y5) + (y6 + y7));

            float act = act_sig(b, ns, amul, aadd);
            float iv = __shfl_sync(0xFFFFFFFFu, act, u_local);
            float fv = __shfl_sync(0xFFFFFFFFu, act, u_local + 5);
            float gv = __shfl_sync(0xFFFFFFFFu, act, u_local + 10);
            float ov = __shfl_sync(0xFFFFFFFFu, act, u_local + 15);
            c1  = fmaf(fv, c1, iv * gv);
            h1r = ov * fast_tanh(c1);
            if (lane < 5) {
                sh_h1[(t - 1) & 1][u] = h1r;        // publish h1(t-1)
                g_h1buf[(t - 1) * HIDN + u] = h1r;
            }
            BAR_L1();                               // group barrier (drains STS)
            if (tid == 128) *vprog1 = t;            // release (consumed slot (t-1)&7)
        }

        // Epilogue: h1(TT-1) from h0(TT-1) and h1(TT-2).
        {
            if (cprog0 < TT - 1) {
                cprog0 = *vprog0;
                while (cprog0 < TT - 1) { __nanosleep(16); cprog0 = *vprog0; }
            }
            COMPILER_FENCE();
            u64 h0p[10], h1p[10];
            ld20p(h0p, sh_h0[(TT - 1) & 7]);   // h0(TT-1)
            ld20p(h1p, sh_h1[TT & 1]);         // h1(TT-2)

            u64 q0 = pack2(b1, 0.f), q1 = 0ULL, q2 = 0ULL, q3 = 0ULL;
            #pragma unroll
            for (int j = 0; j < 5; j++) {
                q0 = ffma2(wi1p[2 * j],     h0p[2 * j],     q0);
                q1 = ffma2(wi1p[2 * j + 1], h0p[2 * j + 1], q1);
                q2 = ffma2(wh1p[2 * j],     h1p[2 * j],     q2);
                q3 = ffma2(wh1p[2 * j + 1], h1p[2 * j + 1], q3);
            }
            float y0, y1, y2, y3, y4, y5, y6, y7;
            unpack2(q0, y0, y1); unpack2(q1, y2, y3);
            unpack2(q2, y4, y5); unpack2(q3, y6, y7);
            float b = ((y0 + y1) + (y2 + y3)) + ((y4 + y5) + (y6 + y7));

            float act = act_sig(b, ns, amul, aadd);
            float iv = __shfl_sync(0xFFFFFFFFu, act, u_local);
            float fv = __shfl_sync(0xFFFFFFFFu, act, u_local + 5);
            float gv = __shfl_sync(0xFFFFFFFFu, act, u_local + 10);
            float ov = __shfl_sync(0xFFFFFFFFu, act, u_local + 15);
            c1  = fmaf(fv, c1, iv * gv);
            h1r = ov * fast_tanh(c1);
            if (lane < 5) {
                g_h1buf[(TT - 1) * HIDN + u] = h1r;
                out_tail[HIDN + u]     = h1r;       // h_n layer 1
                out_tail[3 * HIDN + u] = c1;        // c_n layer 1
            }
        }
    }
}

// ---------------------------------------------------------------------------
// Parallel output pass: out[t] = h1[t] . W_out + b_out
// ---------------------------------------------------------------------------
__global__ void out_kernel(const float* __restrict__ W_out,
                           const float* __restrict__ b_out,
                           float* __restrict__ out) {
    int t = blockIdx.x * blockDim.x + threadIdx.x;
    if (t >= TT) return;
    float wv[HIDN];
    #pragma unroll
    for (int k = 0; k < HIDN; k++) wv[k] = __ldg(&W_out[k]);
    const float4* h4 = reinterpret_cast<const float4*>(&g_h1buf[t * HIDN]);
    float acc = __ldg(b_out);
    #pragma unroll
    for (int i = 0; i < 5; i++) {
        float4 v = __ldg(&h4[i]);
        acc += wv[4 * i] * v.x + wv[4 * i + 1] * v.y
             + wv[4 * i + 2] * v.z + wv[4 * i + 3] * v.w;
    }
    out[t] = acc;
}

extern "C" void kernel_launch(void* const* d_in, const int* in_sizes, int n_in,
                              void* d_out, int out_size) {
    const float* in_states = (const float*)d_in[0];
    const float* W_inp     = (const float*)d_in[1];
    const float* b_inp     = (const float*)d_in[2];
    const float* W_ih0     = (const float*)d_in[3];
    const float* W_hh0     = (const float*)d_in[4];
    const float* b_ih0     = (const float*)d_in[5];
    const float* b_hh0     = (const float*)d_in[6];
    const float* W_ih1     = (const float*)d_in[7];
    const float* W_hh1     = (const float*)d_in[8];
    const float* b_ih1     = (const float*)d_in[9];
    const float* b_hh1     = (const float*)d_in[10];
    const float* W_out     = (const float*)d_in[11];
    const float* b_out     = (const float*)d_in[12];
    float* out = (float*)d_out;

    prep_kernel<<<1, 128>>>(W_inp, b_inp, W_ih0, b_ih0, b_hh0, b_ih1, b_hh1);
    pre0_kernel<<<TT / 4, 320>>>(in_states);
    lstm_seq_kernel<<<1, 256>>>(W_hh0, W_ih1, W_hh1, out + TT);
    out_kernel<<<(TT + 255) / 256, 256>>>(W_out, b_out, out);
}